// round 15
// baseline (speedup 1.0000x reference)
#include <cuda_runtime.h>
#include <cuda_fp16.h>

// Trilinear resample, zero boundary.
// inputs:      [B=2, X=144, Y=144, Z=144, C=2] fp32
// deformation: [B, X, Y, Z, 3] fp32 absolute voxel coords
// output:      [B, X, Y, Z, C] fp32
//
// Per-batch table (47.8 MB, L2-resident), X-FASTEST layout:
// T[y][z][x] = 8 fp16 = 2x2 (y,z) corner block for column x (zero-padded at
// y/z upper edges). A voxel's two x-entries are ADJACENT 16B: even x0 -> one
// 32B v8 gather; odd x0 -> two v4 gathers (lane-predicated, no branches).
// Schedule: expand(b0), main(b0), expand(b1), main(b1) (serial; overlap
// attempts in R13/R14 regressed). Expand = smem transpose for coalescing.

#define SX 144
#define SY 144
#define SZ 144
#define NC 2
#define NB 2
#define VOL (SX * SY * SZ)
#define NPAIRS (VOL / 2)

// Expand tiling: x-tile 16, z-tile 36 (144 = 9*16 = 4*36).
#define XT 16
#define ZT 36

__device__ uint4 g_exp0[(size_t)VOL];
__device__ uint4 g_exp1[(size_t)VOL];

static __device__ __forceinline__ unsigned pack_h2(float2 v) {
    __half2 h = __floats2half2_rn(v.x, v.y);
    return *(unsigned*)&h;
}
static __device__ __forceinline__ float2 unpack_h2(unsigned u) {
    __half2 h = *(__half2*)&u;
    return __half22float2(h);
}

static __device__ __forceinline__ unsigned long long evict_last_policy() {
    unsigned long long pol;
    asm("createpolicy.fractional.L2::evict_last.b64 %0, 1.0;" : "=l"(pol));
    return pol;
}
static __device__ __forceinline__ void st_evict_last(
    uint4* p, uint4 v, unsigned long long pol) {
    asm volatile("st.global.L2::cache_hint.v4.b32 [%0], {%1,%2,%3,%4}, %5;"
                 :: "l"(p), "r"(v.x), "r"(v.y), "r"(v.z), "r"(v.w), "l"(pol)
                 : "memory");
}

// Parity-predicated gather: if even!=0, one 32B v8 load at p0 (32B-aligned);
// else two 16B v4 loads at p0/p1. Every lane takes exactly one path.
static __device__ __forceinline__ void gather_pair(
    const uint4* p0, const uint4* p1, unsigned even, uint4& oA, uint4& oB)
{
    asm("{\n\t"
        ".reg .pred p;\n\t"
        "setp.ne.u32 p, %8, 0;\n\t"
        "@p  ld.global.nc.L2::evict_last.v8.b32 {%0,%1,%2,%3,%4,%5,%6,%7}, [%9];\n\t"
        "@!p ld.global.nc.v4.b32 {%0,%1,%2,%3}, [%9];\n\t"
        "@!p ld.global.nc.v4.b32 {%4,%5,%6,%7}, [%10];\n\t"
        "}"
        : "=r"(oA.x), "=r"(oA.y), "=r"(oA.z), "=r"(oA.w),
          "=r"(oB.x), "=r"(oB.y), "=r"(oB.z), "=r"(oB.w)
        : "r"(even), "l"(p0), "l"(p1));
}

// Expand for one batch into T[y][z][x] via smem transpose.
// Grid: dim3((SX/XT)*(SZ/ZT), SY), 256 threads.
__global__ __launch_bounds__(256) void expand_T(
    const float* __restrict__ inpb, uint4* __restrict__ tab)
{
    __shared__ float2 sm[2][XT][ZT + 2];   // [yo][xo][z offset]

    int y = blockIdx.y;
    int tile = blockIdx.x;
    int x0 = (tile / (SZ / ZT)) * XT;
    int z0 = (tile % (SZ / ZT)) * ZT;

    const float2* vol = (const float2*)inpb;

    // Load phase: rows along z (coalesced). Covers z0..z0+ZT+1, y..y+1.
    for (int i = threadIdx.x; i < 2 * XT * (ZT + 2); i += 256) {
        int zo = i % (ZT + 2);
        int rest = i / (ZT + 2);
        int xo = rest % XT;
        int yo = rest / XT;
        int gy = y + yo, gz = z0 + zo, gx = x0 + xo;
        float2 v = make_float2(0.f, 0.f);
        if (gy < SY && gz < SZ)
            v = vol[((size_t)gx * SY + gy) * SZ + gz];
        sm[yo][xo][zo] = v;
    }
    __syncthreads();

    unsigned long long pol = evict_last_policy();

    // Write phase: runs along x (coalesced 256B) into T[y][z][x].
    for (int i = threadIdx.x; i < XT * ZT; i += 256) {
        int xo = i % XT;
        int zz = i / XT;
        int x = x0 + xo, z = z0 + zz;
        float2 a00 = sm[0][xo][zz];
        float2 a01 = sm[0][xo][zz + 1];  // (y, z+1); zero-padded at SZ edge
        float2 a10 = sm[1][xo][zz];      // (y+1, z); zero-padded at SY edge
        float2 a11 = sm[1][xo][zz + 1];
        uint4 o;
        o.x = pack_h2(a00);
        o.y = pack_h2(a01);
        o.z = pack_h2(a10);
        o.w = pack_h2(a11);
        st_evict_last(&tab[((size_t)y * SZ + z) * SX + x], o, pol);
    }
}

// Per-voxel interpolation with the x-adjacent table.
static __device__ __forceinline__ float2 interp_one(
    const uint4* __restrict__ tab, float cx, float cy, float cz)
{
    float fx = floorf(cx), fy = floorf(cy), fz = floorf(cz);
    int ix0 = (int)fx, iy0 = (int)fy, iz0 = (int)fz;
    float tx = cx - fx, ty = cy - fy, tz = cz - fz;

    float wy0 = 1.0f - ty, wy1 = ty;
    float wz0 = 1.0f - tz, wz1 = tz;
    float w00 = wy0 * wz0, w01 = wy0 * wz1;
    float w10 = wy1 * wz0, w11 = wy1 * wz1;

    bool vyz = (iy0 >= 0) & (iy0 < SY) & (iz0 >= 0) & (iz0 < SZ);
    unsigned cyp = (unsigned)min(max(iy0, 0), SY - 1);
    unsigned czp = (unsigned)min(max(iz0, 0), SZ - 1);

    bool vx0 = (ix0 >= 0) & (ix0 < SX);
    bool vx1 = (ix0 + 1 >= 0) & (ix0 + 1 < SX);
    unsigned cx0 = (unsigned)min(max(ix0, 0), SX - 1);
    unsigned cx1 = (unsigned)min(max(ix0 + 1, 0), SX - 1);

    unsigned base = (cyp * SZ + czp) * (unsigned)SX;
    unsigned off0 = base + cx0;
    unsigned off1 = base + cx1;
    unsigned even = (((cx0 & 1u) == 0u) & (cx1 == cx0 + 1u)) ? 1u : 0u;

    uint4 oA, oB;
    gather_pair(tab + off0, tab + off1, even, oA, oB);

    float wxv0 = (vx0 & vyz) ? (1.0f - tx) : 0.0f;
    float wxv1 = (vx1 & vyz) ? tx : 0.0f;

    float2 a00 = unpack_h2(oA.x), a01 = unpack_h2(oA.y);
    float2 a10 = unpack_h2(oA.z), a11 = unpack_h2(oA.w);
    float2 b00 = unpack_h2(oB.x), b01 = unpack_h2(oB.y);
    float2 b10 = unpack_h2(oB.z), b11 = unpack_h2(oB.w);

    float sA0 = w00 * a00.x + w01 * a01.x + w10 * a10.x + w11 * a11.x;
    float sA1 = w00 * a00.y + w01 * a01.y + w10 * a10.y + w11 * a11.y;
    float sB0 = w00 * b00.x + w01 * b01.x + w10 * b10.x + w11 * b11.x;
    float sB1 = w00 * b00.y + w01 * b01.y + w10 * b10.y + w11 * b11.y;

    return make_float2(wxv0 * sA0 + wxv1 * sB0,
                       wxv0 * sA1 + wxv1 * sB1);
}

__global__ __launch_bounds__(256) void resample_main2(
    const float* __restrict__ defb,
    float* __restrict__ outb,
    const uint4* __restrict__ tab,
    int npairs)  // VOL/2
{
    int t = blockIdx.x * blockDim.x + threadIdx.x;
    if (t >= npairs) return;

    const float2* dp = (const float2*)(defb + (size_t)(2 * t) * 3);
    float2 d0 = __ldcs(dp + 0);  // cx0, cy0
    float2 d1 = __ldcs(dp + 1);  // cz0, cx1
    float2 d2 = __ldcs(dp + 2);  // cy1, cz1

    float2 r0 = interp_one(tab, d0.x, d0.y, d1.x);
    float2 r1 = interp_one(tab, d1.y, d2.x, d2.y);

    __stcs((float4*)outb + t, make_float4(r0.x, r0.y, r1.x, r1.y));
}

// Exact fallback (R2 kernel) in case sizes differ from the expected shape.
__global__ __launch_bounds__(256) void resample_fallback(
    const float* __restrict__ inp,
    const float* __restrict__ def,
    float* __restrict__ out,
    int total)
{
    int idx = blockIdx.x * blockDim.x + threadIdx.x;
    if (idx >= total) return;
    int b = idx / VOL;
    const float* d = def + (size_t)idx * 3;
    float cx = __ldg(d + 0), cy = __ldg(d + 1), cz = __ldg(d + 2);
    float fx = floorf(cx), fy = floorf(cy), fz = floorf(cz);
    int ix0 = (int)fx, iy0 = (int)fy, iz0 = (int)fz;
    float tx = cx - fx, ty = cy - fy, tz = cz - fz;
    float wxw[2] = {1.0f - tx, tx};
    float wyw[2] = {1.0f - ty, ty};
    float wzw[2] = {1.0f - tz, tz};
    const float* base = inp + (size_t)b * VOL * NC;
    float acc0 = 0.f, acc1 = 0.f;
#pragma unroll
    for (int dx = 0; dx < 2; dx++) {
        int ix = ix0 + dx;
        bool vx = (ix >= 0) & (ix < SX);
        int cxp = min(max(ix, 0), SX - 1);
#pragma unroll
        for (int dy = 0; dy < 2; dy++) {
            int iy = iy0 + dy;
            bool vxy = vx & (iy >= 0) & (iy < SY);
            int cyp = min(max(iy, 0), SY - 1);
            float wxy = wxw[dx] * wyw[dy];
            const float* row = base + ((size_t)cxp * SY + cyp) * SZ * NC;
#pragma unroll
            for (int dz = 0; dz < 2; dz++) {
                int iz = iz0 + dz;
                bool v = vxy & (iz >= 0) & (iz < SZ);
                int czp = min(max(iz, 0), SZ - 1);
                float2 val = __ldg((const float2*)(row + (size_t)czp * NC));
                float w = v ? (wxy * wzw[dz]) : 0.0f;
                acc0 = fmaf(w, val.x, acc0);
                acc1 = fmaf(w, val.y, acc1);
            }
        }
    }
    ((float2*)out)[idx] = make_float2(acc0, acc1);
}

extern "C" void kernel_launch(void* const* d_in, const int* in_sizes, int n_in,
                              void* d_out, int out_size)
{
    int total = out_size / NC;

    const float* inp = (const float*)d_in[0];
    const float* def = (const float*)d_in[1];
    if (n_in >= 2) {
        long long t = (long long)total;
        if ((long long)in_sizes[0] == 3LL * t && (long long)in_sizes[1] == 2LL * t) {
            def = (const float*)d_in[0];
            inp = (const float*)d_in[1];
        }
    }

    const int threads = 256;

    if (total == NB * VOL) {
        uint4* tab0;  cudaGetSymbolAddress((void**)&tab0, g_exp0);
        uint4* tab1;  cudaGetSymbolAddress((void**)&tab1, g_exp1);

        dim3 gridE((SX / XT) * (SZ / ZT), SY);
        int blocksM = (NPAIRS + threads - 1) / threads;

        uint4* tabs[2] = {tab0, tab1};
        for (int b = 0; b < NB; b++) {
            expand_T<<<gridE, threads>>>(inp + (size_t)b * VOL * NC, tabs[b]);
            resample_main2<<<blocksM, threads>>>(
                def + (size_t)b * VOL * 3,
                (float*)d_out + (size_t)b * VOL * NC,
                tabs[b], NPAIRS);
        }
    } else {
        int blocks = (total + threads - 1) / threads;
        resample_fallback<<<blocks, threads>>>(inp, def, (float*)d_out, total);
    }
}

// round 16
// speedup vs baseline: 1.1774x; 1.1774x over previous
#include <cuda_runtime.h>
#include <cuda_fp16.h>

// Trilinear resample, zero boundary.
// inputs:      [B=2, X=144, Y=144, Z=144, C=2] fp32
// deformation: [B, X, Y, Z, 3] fp32 absolute voxel coords
// output:      [B, X, Y, Z, C] fp32
//
// Per-batch table (47.8 MB, L2-resident), Z-FASTEST layout with (x,y)-block
// entries: T[x][y][z] = 8 fp16 = the 2x2 (x,y) corner block at depth z
// (ch0,ch1 per corner; zero-padded at x/y upper edges). A voxel's two
// z-entries are ADJACENT 16B: even z0 -> one 32B v8 gather; odd z0 -> two
// v4 gathers (lane-predicated, branch-free). Expand keeps the cheap
// coalesced z-row structure (no transpose). Serial schedule per batch.

#define SX 144
#define SY 144
#define SZ 144
#define NC 2
#define NB 2
#define VOL (SX * SY * SZ)
#define NPAIRS (VOL / 2)

__device__ uint4 g_exp0[(size_t)VOL];
__device__ uint4 g_exp1[(size_t)VOL];

static __device__ __forceinline__ unsigned pack_h2(float2 v) {
    __half2 h = __floats2half2_rn(v.x, v.y);
    return *(unsigned*)&h;
}
static __device__ __forceinline__ float2 unpack_h2(unsigned u) {
    __half2 h = *(__half2*)&u;
    return __half22float2(h);
}

static __device__ __forceinline__ unsigned long long evict_last_policy() {
    unsigned long long pol;
    asm("createpolicy.fractional.L2::evict_last.b64 %0, 1.0;" : "=l"(pol));
    return pol;
}
static __device__ __forceinline__ void st_evict_last(
    uint4* p, uint4 v, unsigned long long pol) {
    asm volatile("st.global.L2::cache_hint.v4.b32 [%0], {%1,%2,%3,%4}, %5;"
                 :: "l"(p), "r"(v.x), "r"(v.y), "r"(v.z), "r"(v.w), "l"(pol)
                 : "memory");
}

// Parity-predicated gather: if even!=0, one 32B v8 load at p0 (32B-aligned);
// else two 16B v4 loads at p0/p1. Every lane takes exactly one path.
static __device__ __forceinline__ void gather_pair(
    const uint4* p0, const uint4* p1, unsigned even, uint4& oA, uint4& oB)
{
    asm("{\n\t"
        ".reg .pred p;\n\t"
        "setp.ne.u32 p, %8, 0;\n\t"
        "@p  ld.global.nc.L2::evict_last.v8.b32 {%0,%1,%2,%3,%4,%5,%6,%7}, [%9];\n\t"
        "@!p ld.global.nc.v4.b32 {%0,%1,%2,%3}, [%9];\n\t"
        "@!p ld.global.nc.v4.b32 {%4,%5,%6,%7}, [%10];\n\t"
        "}"
        : "=r"(oA.x), "=r"(oA.y), "=r"(oA.z), "=r"(oA.w),
          "=r"(oB.x), "=r"(oB.y), "=r"(oB.z), "=r"(oB.w)
        : "r"(even), "l"(p0), "l"(p1));
}

// Expand for one batch: entry idx = x*SY*SZ + y*SZ + z (z-fastest, same
// order as the volume -> coalesced reads AND writes, no transpose).
// Entry holds the 2x2 (x,y) block at this z.
__global__ __launch_bounds__(256) void expand_kernel(
    const float* __restrict__ inpb, uint4* __restrict__ tab, int n)  // n=VOL
{
    int idx = blockIdx.x * blockDim.x + threadIdx.x;
    if (idx >= n) return;

    int r = idx / SZ;        // = x*SY + y
    int y = r % SY;
    int x = r / SY;

    bool xv = (x + 1 < SX);
    bool yv = (y + 1 < SY);

    const float* p00 = inpb + (size_t)idx * NC;            // (x,   y,   z)
    float2 v00 = *(const float2*)p00;
    float2 v01 = yv ? *(const float2*)(p00 + SZ * NC)       // (x,   y+1, z)
                    : make_float2(0.f, 0.f);
    float2 v10 = xv ? *(const float2*)(p00 + SY * SZ * NC)  // (x+1, y,   z)
                    : make_float2(0.f, 0.f);
    float2 v11 = (xv && yv)
                    ? *(const float2*)(p00 + (SY * SZ + SZ) * NC)
                    : make_float2(0.f, 0.f);                 // (x+1, y+1, z)

    uint4 o;
    o.x = pack_h2(v00);   // (x,   y)
    o.y = pack_h2(v01);   // (x,   y+1)
    o.z = pack_h2(v10);   // (x+1, y)
    o.w = pack_h2(v11);   // (x+1, y+1)
    st_evict_last(&tab[idx], o, evict_last_policy());
}

// Per-voxel interpolation: z-adjacent entry pair, parity-predicated gather.
static __device__ __forceinline__ float2 interp_one(
    const uint4* __restrict__ tab, float cx, float cy, float cz)
{
    float fx = floorf(cx), fy = floorf(cy), fz = floorf(cz);
    int ix0 = (int)fx, iy0 = (int)fy, iz0 = (int)fz;
    float tx = cx - fx, ty = cy - fy, tz = cz - fz;

    float wx0 = 1.0f - tx, wx1 = tx;
    float wy0 = 1.0f - ty, wy1 = ty;

    // 2x2 (x,y) corner weights; entry zero-padding covers x+1/y+1 overflow.
    float q00 = wx0 * wy0, q01 = wx0 * wy1;
    float q10 = wx1 * wy0, q11 = wx1 * wy1;

    bool vxy = (ix0 >= 0) & (ix0 < SX) & (iy0 >= 0) & (iy0 < SY);
    unsigned cxp = (unsigned)min(max(ix0, 0), SX - 1);
    unsigned cyp = (unsigned)min(max(iy0, 0), SY - 1);

    bool vz0 = (iz0 >= 0) & (iz0 < SZ);
    bool vz1 = (iz0 + 1 >= 0) & (iz0 + 1 < SZ);
    unsigned cz0 = (unsigned)min(max(iz0, 0), SZ - 1);
    unsigned cz1 = (unsigned)min(max(iz0 + 1, 0), SZ - 1);

    unsigned base = (cxp * SY + cyp) * (unsigned)SZ;
    unsigned off0 = base + cz0;
    unsigned off1 = base + cz1;
    unsigned even = (((cz0 & 1u) == 0u) & (cz1 == cz0 + 1u)) ? 1u : 0u;

    uint4 oA, oB;
    gather_pair(tab + off0, tab + off1, even, oA, oB);

    // z-slot weights (validity folded; clamped-entry trick covers iz0 == -1).
    float wA = (vz0 & vxy) ? (1.0f - tz) : 0.0f;
    float wB = (vz1 & vxy) ? tz : 0.0f;

    float2 a00 = unpack_h2(oA.x), a01 = unpack_h2(oA.y);
    float2 a10 = unpack_h2(oA.z), a11 = unpack_h2(oA.w);
    float2 b00 = unpack_h2(oB.x), b01 = unpack_h2(oB.y);
    float2 b10 = unpack_h2(oB.z), b11 = unpack_h2(oB.w);

    float sA0 = q00 * a00.x + q01 * a01.x + q10 * a10.x + q11 * a11.x;
    float sA1 = q00 * a00.y + q01 * a01.y + q10 * a10.y + q11 * a11.y;
    float sB0 = q00 * b00.x + q01 * b01.x + q10 * b10.x + q11 * b11.x;
    float sB1 = q00 * b00.y + q01 * b01.y + q10 * b10.y + q11 * b11.y;

    return make_float2(wA * sA0 + wB * sB0,
                       wA * sA1 + wB * sB1);
}

__global__ __launch_bounds__(256) void resample_main2(
    const float* __restrict__ defb,
    float* __restrict__ outb,
    const uint4* __restrict__ tab,
    int npairs)  // VOL/2
{
    int t = blockIdx.x * blockDim.x + threadIdx.x;
    if (t >= npairs) return;

    const float2* dp = (const float2*)(defb + (size_t)(2 * t) * 3);
    float2 d0 = __ldcs(dp + 0);  // cx0, cy0
    float2 d1 = __ldcs(dp + 1);  // cz0, cx1
    float2 d2 = __ldcs(dp + 2);  // cy1, cz1

    float2 r0 = interp_one(tab, d0.x, d0.y, d1.x);
    float2 r1 = interp_one(tab, d1.y, d2.x, d2.y);

    __stcs((float4*)outb + t, make_float4(r0.x, r0.y, r1.x, r1.y));
}

// Exact fallback (R2 kernel) in case sizes differ from the expected shape.
__global__ __launch_bounds__(256) void resample_fallback(
    const float* __restrict__ inp,
    const float* __restrict__ def,
    float* __restrict__ out,
    int total)
{
    int idx = blockIdx.x * blockDim.x + threadIdx.x;
    if (idx >= total) return;
    int b = idx / VOL;
    const float* d = def + (size_t)idx * 3;
    float cx = __ldg(d + 0), cy = __ldg(d + 1), cz = __ldg(d + 2);
    float fx = floorf(cx), fy = floorf(cy), fz = floorf(cz);
    int ix0 = (int)fx, iy0 = (int)fy, iz0 = (int)fz;
    float tx = cx - fx, ty = cy - fy, tz = cz - fz;
    float wxw[2] = {1.0f - tx, tx};
    float wyw[2] = {1.0f - ty, ty};
    float wzw[2] = {1.0f - tz, tz};
    const float* base = inp + (size_t)b * VOL * NC;
    float acc0 = 0.f, acc1 = 0.f;
#pragma unroll
    for (int dx = 0; dx < 2; dx++) {
        int ix = ix0 + dx;
        bool vx = (ix >= 0) & (ix < SX);
        int cxp = min(max(ix, 0), SX - 1);
#pragma unroll
        for (int dy = 0; dy < 2; dy++) {
            int iy = iy0 + dy;
            bool vxy = vx & (iy >= 0) & (iy < SY);
            int cyp = min(max(iy, 0), SY - 1);
            float wxy = wxw[dx] * wyw[dy];
            const float* row = base + ((size_t)cxp * SY + cyp) * SZ * NC;
#pragma unroll
            for (int dz = 0; dz < 2; dz++) {
                int iz = iz0 + dz;
                bool v = vxy & (iz >= 0) & (iz < SZ);
                int czp = min(max(iz, 0), SZ - 1);
                float2 val = __ldg((const float2*)(row + (size_t)czp * NC));
                float w = v ? (wxy * wzw[dz]) : 0.0f;
                acc0 = fmaf(w, val.x, acc0);
                acc1 = fmaf(w, val.y, acc1);
            }
        }
    }
    ((float2*)out)[idx] = make_float2(acc0, acc1);
}

extern "C" void kernel_launch(void* const* d_in, const int* in_sizes, int n_in,
                              void* d_out, int out_size)
{
    int total = out_size / NC;

    const float* inp = (const float*)d_in[0];
    const float* def = (const float*)d_in[1];
    if (n_in >= 2) {
        long long t = (long long)total;
        if ((long long)in_sizes[0] == 3LL * t && (long long)in_sizes[1] == 2LL * t) {
            def = (const float*)d_in[0];
            inp = (const float*)d_in[1];
        }
    }

    const int threads = 256;

    if (total == NB * VOL) {
        uint4* tab0;  cudaGetSymbolAddress((void**)&tab0, g_exp0);
        uint4* tab1;  cudaGetSymbolAddress((void**)&tab1, g_exp1);

        int blocksE = (VOL + threads - 1) / threads;
        int blocksM = (NPAIRS + threads - 1) / threads;

        uint4* tabs[2] = {tab0, tab1};
        for (int b = 0; b < NB; b++) {
            expand_kernel<<<blocksE, threads>>>(
                inp + (size_t)b * VOL * NC, tabs[b], VOL);
            resample_main2<<<blocksM, threads>>>(
                def + (size_t)b * VOL * 3,
                (float*)d_out + (size_t)b * VOL * NC,
                tabs[b], NPAIRS);
        }
    } else {
        int blocks = (total + threads - 1) / threads;
        resample_fallback<<<blocks, threads>>>(inp, def, (float*)d_out, total);
    }
}

// round 17
// speedup vs baseline: 1.2402x; 1.0534x over previous
#include <cuda_runtime.h>
#include <cuda_fp16.h>

// Trilinear resample, zero boundary.
// inputs:      [B=2, X=144, Y=144, Z=144, C=2] fp32
// deformation: [B, X, Y, Z, 3] fp32 absolute voxel coords
// output:      [B, X, Y, Z, C] fp32
//
// Per-batch table (47.8 MB, L2-resident), Z-FASTEST layout with (x,y)-block
// entries: T[x][y][z] = 8 fp16 = the 2x2 (x,y) corner block at depth z
// (zero-padded at x/y upper edges). A voxel's two z-entries are ADJACENT
// 16B: even z0 -> one 32B v8 gather; odd z0 -> two v4 gathers (lane-
// predicated, branch-free). Expand: 2 z-entries/thread, float4 row reads,
// one v8 store. Serial schedule per batch.

#define SX 144
#define SY 144
#define SZ 144
#define NC 2
#define NB 2
#define VOL (SX * SY * SZ)
#define NPAIRS (VOL / 2)

__device__ uint4 g_exp0[(size_t)VOL];
__device__ uint4 g_exp1[(size_t)VOL];

static __device__ __forceinline__ unsigned pack_h2(float a, float b) {
    __half2 h = __floats2half2_rn(a, b);
    return *(unsigned*)&h;
}
static __device__ __forceinline__ float2 unpack_h2(unsigned u) {
    __half2 h = *(__half2*)&u;
    return __half22float2(h);
}

static __device__ __forceinline__ void st_v8_evict_last(
    uint4* p, const unsigned r[8]) {
    asm volatile(
        "st.global.L2::evict_last.v8.b32 [%0], {%1,%2,%3,%4,%5,%6,%7,%8};"
        :: "l"(p), "r"(r[0]), "r"(r[1]), "r"(r[2]), "r"(r[3]),
           "r"(r[4]), "r"(r[5]), "r"(r[6]), "r"(r[7]) : "memory");
}

// Parity-predicated gather: if even!=0, one 32B v8 load at p0 (32B-aligned);
// else two 16B v4 loads at p0/p1. Every lane takes exactly one path.
static __device__ __forceinline__ void gather_pair(
    const uint4* p0, const uint4* p1, unsigned even, uint4& oA, uint4& oB)
{
    asm("{\n\t"
        ".reg .pred p;\n\t"
        "setp.ne.u32 p, %8, 0;\n\t"
        "@p  ld.global.nc.L2::evict_last.v8.b32 {%0,%1,%2,%3,%4,%5,%6,%7}, [%9];\n\t"
        "@!p ld.global.nc.v4.b32 {%0,%1,%2,%3}, [%9];\n\t"
        "@!p ld.global.nc.v4.b32 {%4,%5,%6,%7}, [%10];\n\t"
        "}"
        : "=r"(oA.x), "=r"(oA.y), "=r"(oA.z), "=r"(oA.w),
          "=r"(oB.x), "=r"(oB.y), "=r"(oB.z), "=r"(oB.w)
        : "r"(even), "l"(p0), "l"(p1));
}

// Expand for one batch: 2 consecutive-z entries per thread (z even; SZ even
// so a thread never crosses a row). Entry idx = x*SY*SZ + y*SZ + z holds the
// 2x2 (x,y) block at depth z. float4 reads cover both z's per row; the two
// entries store as ONE 32B v8 store.
__global__ __launch_bounds__(256) void expand_kernel2(
    const float* __restrict__ inpb, uint4* __restrict__ tab, int npairs)
{
    int t = blockIdx.x * blockDim.x + threadIdx.x;
    if (t >= npairs) return;

    int idx = 2 * t;         // first entry (z even)
    int r = idx / SZ;        // = x*SY + y
    int y = r % SY;
    int x = r / SY;

    bool xv = (x + 1 < SX);
    bool yv = (y + 1 < SY);

    const float* p00 = inpb + (size_t)idx * NC;  // (x, y, z)
    const float4 zero4 = make_float4(0.f, 0.f, 0.f, 0.f);

    float4 v00 = *(const float4*)p00;                           // z,z+1 @(x,y)
    float4 v01 = yv ? *(const float4*)(p00 + SZ * NC) : zero4;   // (x,y+1)
    float4 v10 = xv ? *(const float4*)(p00 + SY * SZ * NC) : zero4;
    float4 v11 = (xv && yv) ? *(const float4*)(p00 + (SY * SZ + SZ) * NC)
                            : zero4;

    unsigned e[8];
    e[0] = pack_h2(v00.x, v00.y);   // entry z: (x,  y)
    e[1] = pack_h2(v01.x, v01.y);   //          (x,  y+1)
    e[2] = pack_h2(v10.x, v10.y);   //          (x+1,y)
    e[3] = pack_h2(v11.x, v11.y);   //          (x+1,y+1)
    e[4] = pack_h2(v00.z, v00.w);   // entry z+1
    e[5] = pack_h2(v01.z, v01.w);
    e[6] = pack_h2(v10.z, v10.w);
    e[7] = pack_h2(v11.z, v11.w);
    st_v8_evict_last(&tab[idx], e);
}

// Per-voxel interpolation: z-adjacent entry pair, parity-predicated gather.
static __device__ __forceinline__ float2 interp_one(
    const uint4* __restrict__ tab, float cx, float cy, float cz)
{
    float fx = floorf(cx), fy = floorf(cy), fz = floorf(cz);
    int ix0 = (int)fx, iy0 = (int)fy, iz0 = (int)fz;
    float tx = cx - fx, ty = cy - fy, tz = cz - fz;

    float wx0 = 1.0f - tx, wx1 = tx;
    float wy0 = 1.0f - ty, wy1 = ty;

    float q00 = wx0 * wy0, q01 = wx0 * wy1;
    float q10 = wx1 * wy0, q11 = wx1 * wy1;

    bool vxy = (ix0 >= 0) & (ix0 < SX) & (iy0 >= 0) & (iy0 < SY);
    unsigned cxp = (unsigned)min(max(ix0, 0), SX - 1);
    unsigned cyp = (unsigned)min(max(iy0, 0), SY - 1);

    bool vz0 = (iz0 >= 0) & (iz0 < SZ);
    bool vz1 = (iz0 + 1 >= 0) & (iz0 + 1 < SZ);
    unsigned cz0 = (unsigned)min(max(iz0, 0), SZ - 1);
    unsigned cz1 = (unsigned)min(max(iz0 + 1, 0), SZ - 1);

    unsigned base = (cxp * SY + cyp) * (unsigned)SZ;
    unsigned off0 = base + cz0;
    unsigned off1 = base + cz1;
    unsigned even = (((cz0 & 1u) == 0u) & (cz1 == cz0 + 1u)) ? 1u : 0u;

    uint4 oA, oB;
    gather_pair(tab + off0, tab + off1, even, oA, oB);

    float wA = (vz0 & vxy) ? (1.0f - tz) : 0.0f;
    float wB = (vz1 & vxy) ? tz : 0.0f;

    float2 a00 = unpack_h2(oA.x), a01 = unpack_h2(oA.y);
    float2 a10 = unpack_h2(oA.z), a11 = unpack_h2(oA.w);
    float2 b00 = unpack_h2(oB.x), b01 = unpack_h2(oB.y);
    float2 b10 = unpack_h2(oB.z), b11 = unpack_h2(oB.w);

    float sA0 = q00 * a00.x + q01 * a01.x + q10 * a10.x + q11 * a11.x;
    float sA1 = q00 * a00.y + q01 * a01.y + q10 * a10.y + q11 * a11.y;
    float sB0 = q00 * b00.x + q01 * b01.x + q10 * b10.x + q11 * b11.x;
    float sB1 = q00 * b00.y + q01 * b01.y + q10 * b10.y + q11 * b11.y;

    return make_float2(wA * sA0 + wB * sB0,
                       wA * sA1 + wB * sB1);
}

__global__ __launch_bounds__(256, 7) void resample_main2(
    const float* __restrict__ defb,
    float* __restrict__ outb,
    const uint4* __restrict__ tab,
    int npairs)  // VOL/2
{
    int t = blockIdx.x * blockDim.x + threadIdx.x;
    if (t >= npairs) return;

    const float2* dp = (const float2*)(defb + (size_t)(2 * t) * 3);
    float2 d0 = __ldcs(dp + 0);  // cx0, cy0
    float2 d1 = __ldcs(dp + 1);  // cz0, cx1
    float2 d2 = __ldcs(dp + 2);  // cy1, cz1

    float2 r0 = interp_one(tab, d0.x, d0.y, d1.x);
    float2 r1 = interp_one(tab, d1.y, d2.x, d2.y);

    __stcs((float4*)outb + t, make_float4(r0.x, r0.y, r1.x, r1.y));
}

// Exact fallback (R2 kernel) in case sizes differ from the expected shape.
__global__ __launch_bounds__(256) void resample_fallback(
    const float* __restrict__ inp,
    const float* __restrict__ def,
    float* __restrict__ out,
    int total)
{
    int idx = blockIdx.x * blockDim.x + threadIdx.x;
    if (idx >= total) return;
    int b = idx / VOL;
    const float* d = def + (size_t)idx * 3;
    float cx = __ldg(d + 0), cy = __ldg(d + 1), cz = __ldg(d + 2);
    float fx = floorf(cx), fy = floorf(cy), fz = floorf(cz);
    int ix0 = (int)fx, iy0 = (int)fy, iz0 = (int)fz;
    float tx = cx - fx, ty = cy - fy, tz = cz - fz;
    float wxw[2] = {1.0f - tx, tx};
    float wyw[2] = {1.0f - ty, ty};
    float wzw[2] = {1.0f - tz, tz};
    const float* base = inp + (size_t)b * VOL * NC;
    float acc0 = 0.f, acc1 = 0.f;
#pragma unroll
    for (int dx = 0; dx < 2; dx++) {
        int ix = ix0 + dx;
        bool vx = (ix >= 0) & (ix < SX);
        int cxp = min(max(ix, 0), SX - 1);
#pragma unroll
        for (int dy = 0; dy < 2; dy++) {
            int iy = iy0 + dy;
            bool vxy = vx & (iy >= 0) & (iy < SY);
            int cyp = min(max(iy, 0), SY - 1);
            float wxy = wxw[dx] * wyw[dy];
            const float* row = base + ((size_t)cxp * SY + cyp) * SZ * NC;
#pragma unroll
            for (int dz = 0; dz < 2; dz++) {
                int iz = iz0 + dz;
                bool v = vxy & (iz >= 0) & (iz < SZ);
                int czp = min(max(iz, 0), SZ - 1);
                float2 val = __ldg((const float2*)(row + (size_t)czp * NC));
                float w = v ? (wxy * wzw[dz]) : 0.0f;
                acc0 = fmaf(w, val.x, acc0);
                acc1 = fmaf(w, val.y, acc1);
            }
        }
    }
    ((float2*)out)[idx] = make_float2(acc0, acc1);
}

extern "C" void kernel_launch(void* const* d_in, const int* in_sizes, int n_in,
                              void* d_out, int out_size)
{
    int total = out_size / NC;

    const float* inp = (const float*)d_in[0];
    const float* def = (const float*)d_in[1];
    if (n_in >= 2) {
        long long t = (long long)total;
        if ((long long)in_sizes[0] == 3LL * t && (long long)in_sizes[1] == 2LL * t) {
            def = (const float*)d_in[0];
            inp = (const float*)d_in[1];
        }
    }

    const int threads = 256;

    if (total == NB * VOL) {
        uint4* tab0;  cudaGetSymbolAddress((void**)&tab0, g_exp0);
        uint4* tab1;  cudaGetSymbolAddress((void**)&tab1, g_exp1);

        int blocksE = (NPAIRS + threads - 1) / threads;
        int blocksM = (NPAIRS + threads - 1) / threads;

        uint4* tabs[2] = {tab0, tab1};
        for (int b = 0; b < NB; b++) {
            expand_kernel2<<<blocksE, threads>>>(
                inp + (size_t)b * VOL * NC, tabs[b], NPAIRS);
            resample_main2<<<blocksM, threads>>>(
                def + (size_t)b * VOL * 3,
                (float*)d_out + (size_t)b * VOL * NC,
                tabs[b], NPAIRS);
        }
    } else {
        int blocks = (total + threads - 1) / threads;
        resample_fallback<<<blocks, threads>>>(inp, def, (float*)d_out, total);
    }
}